// round 3
// baseline (speedup 1.0000x reference)
#include <cuda_runtime.h>
#include <math_constants.h>
#include <math.h>

#define NN 100000
#define NE 1600000
#define FIN 256
#define FH 256
#define NC 40

// ---------------- scratch (static device globals; no allocation) ------------
__device__ float g_deg[NN];
__device__ float g_dis[NN];
__device__ int   g_count[NN];
__device__ int   g_rowptr[NN];
__device__ int   g_cursor[NN];
__device__ int   g_esrc[NE];
__device__ float g_enorm[NE];
__device__ float g_h1[(size_t)NN * FH];   // x @ W1 + b1
__device__ float g_a1[(size_t)NN * FH];   // relu(aggregate(h1))
__device__ float g_h2[(size_t)NN * NC];   // a1 @ W2 + b2

// ---------------- graph preprocessing ---------------------------------------
__global__ void k_init() {
    int i = blockIdx.x * blockDim.x + threadIdx.x;
    if (i < NN) { g_deg[i] = 1.0f; g_count[i] = 0; }   // self-loop weight 1
}

__global__ void k_deg(const int* __restrict__ dst, const float* __restrict__ ew) {
    int e = blockIdx.x * blockDim.x + threadIdx.x;
    if (e < NE) {
        int d = dst[e];
        atomicAdd(&g_deg[d], ew[e]);
        atomicAdd(&g_count[d], 1);
    }
}

__global__ void k_dis() {
    int i = blockIdx.x * blockDim.x + threadIdx.x;
    if (i < NN) g_dis[i] = rsqrtf(g_deg[i]);   // deg >= 1 always (self loop)
}

// single-block exclusive scan of g_count -> g_rowptr (and cursor copy)
__global__ void k_scan() {
    __shared__ int sh[1024];
    int tid = threadIdx.x;
    int carry = 0;
    for (int base = 0; base < NN; base += 1024) {
        int i = base + tid;
        int v = (i < NN) ? g_count[i] : 0;
        sh[tid] = v;
        __syncthreads();
        #pragma unroll
        for (int off = 1; off < 1024; off <<= 1) {
            int t = (tid >= off) ? sh[tid - off] : 0;
            __syncthreads();
            sh[tid] += t;
            __syncthreads();
        }
        int inc = sh[tid];
        if (i < NN) {
            int ex = carry + inc - v;
            g_rowptr[i] = ex;
            g_cursor[i] = ex;
        }
        int total = sh[1023];
        __syncthreads();
        carry += total;
    }
}

__global__ void k_scatter(const int* __restrict__ src, const int* __restrict__ dst,
                          const float* __restrict__ ew) {
    int e = blockIdx.x * blockDim.x + threadIdx.x;
    if (e < NE) {
        int s = src[e], d = dst[e];
        int p = atomicAdd(&g_cursor[d], 1);
        g_esrc[p]  = s;
        g_enorm[p] = g_dis[s] * ew[e] * g_dis[d];
    }
}

// ---------------- big-tile fp32 GEMM for layer 1 ----------------------------
// C[M,256] = A[M,256] @ B[256,256] + bias. 128x128 tile, BK=8, 8x8/thread.
// Requires N % 128 == 0 and K % 8 == 0 (true for layer 1). M edge guarded.
__global__ void k_gemm128(const float* __restrict__ A, const float* __restrict__ B,
                          const float* __restrict__ bias, float* __restrict__ C,
                          int M, int N, int K) {
    __shared__ float As[8][128];
    __shared__ float Bs[8][128];
    int tid = threadIdx.x;
    int m0 = blockIdx.x * 128;
    int n0 = blockIdx.y * 128;

    int ar = tid >> 1;              // A load row 0..127
    int ak = (tid & 1) << 2;        // A load k 0 or 4
    int bk = tid >> 5;              // B load k 0..7
    int bc = (tid & 31) << 2;       // B load col 0..124

    int tx = tid & 15;              // 0..15 -> n
    int ty = tid >> 4;              // 0..15 -> m

    float acc[8][8] = {};

    for (int k0 = 0; k0 < K; k0 += 8) {
        float4 av = make_float4(0.f, 0.f, 0.f, 0.f);
        int arow = m0 + ar;
        if (arow < M)
            av = *(const float4*)(A + (size_t)arow * K + k0 + ak);
        As[ak + 0][ar] = av.x;
        As[ak + 1][ar] = av.y;
        As[ak + 2][ar] = av.z;
        As[ak + 3][ar] = av.w;

        float4 bv = *(const float4*)(B + (size_t)(k0 + bk) * N + n0 + bc);
        *(float4*)&Bs[bk][bc] = bv;
        __syncthreads();

        #pragma unroll
        for (int kk = 0; kk < 8; kk++) {
            float a[8], b[8];
            *(float4*)&a[0] = *(float4*)&As[kk][ty << 3];
            *(float4*)&a[4] = *(float4*)&As[kk][(ty << 3) + 4];
            *(float4*)&b[0] = *(float4*)&Bs[kk][tx << 3];
            *(float4*)&b[4] = *(float4*)&Bs[kk][(tx << 3) + 4];
            #pragma unroll
            for (int i = 0; i < 8; i++)
                #pragma unroll
                for (int j = 0; j < 8; j++)
                    acc[i][j] += a[i] * b[j];
        }
        __syncthreads();
    }

    #pragma unroll
    for (int i = 0; i < 8; i++) {
        int m = m0 + (ty << 3) + i;
        if (m >= M) continue;
        float* crow = C + (size_t)m * N + n0 + (tx << 3);
        const float* brow = bias + n0 + (tx << 3);
        #pragma unroll
        for (int j = 0; j < 8; j++)
            crow[j] = acc[i][j] + brow[j];
    }
}

// ---------------- SIMT fp32 GEMM (guarded; used for layer 2, N=40) ----------
// 64x64 block tile, BK=16, 4x4 thread tile, 256 threads
__global__ void k_gemm(const float* __restrict__ A, const float* __restrict__ B,
                       const float* __restrict__ bias, float* __restrict__ C,
                       int M, int N, int K) {
    __shared__ float As[16][64];   // transposed: As[k][m]
    __shared__ float Bs[16][64];   // Bs[k][n]
    int tid = threadIdx.x;
    int m0 = blockIdx.x * 64;
    int n0 = blockIdx.y * 64;
    int tr = tid >> 4;            // 0..15
    int tc = tid & 15;            // 0..15

    int lr = tid >> 2;            // A load: row 0..63
    int lk = (tid & 3) << 2;      // A load: k offset 0,4,8,12
    int bkr = tid >> 4;           // B load: k row 0..15
    int bc  = (tid & 15) << 2;    // B load: col 0..60

    float acc[4][4] = {};

    for (int k0 = 0; k0 < K; k0 += 16) {
        float4 av = make_float4(0.f, 0.f, 0.f, 0.f);
        int arow = m0 + lr;
        if (arow < M)
            av = *(const float4*)(A + (size_t)arow * K + k0 + lk);
        As[lk + 0][lr] = av.x;
        As[lk + 1][lr] = av.y;
        As[lk + 2][lr] = av.z;
        As[lk + 3][lr] = av.w;

        float4 bv = make_float4(0.f, 0.f, 0.f, 0.f);
        if (n0 + bc + 3 < N)
            bv = *(const float4*)(B + (size_t)(k0 + bkr) * N + n0 + bc);
        *(float4*)&Bs[bkr][bc] = bv;
        __syncthreads();

        #pragma unroll
        for (int kk = 0; kk < 16; kk++) {
            float4 a = *(float4*)&As[kk][tr << 2];
            float4 b = *(float4*)&Bs[kk][tc << 2];
            float ar[4] = {a.x, a.y, a.z, a.w};
            float br[4] = {b.x, b.y, b.z, b.w};
            #pragma unroll
            for (int i = 0; i < 4; i++)
                #pragma unroll
                for (int j = 0; j < 4; j++)
                    acc[i][j] += ar[i] * br[j];
        }
        __syncthreads();
    }

    #pragma unroll
    for (int i = 0; i < 4; i++) {
        int m = m0 + (tr << 2) + i;
        if (m >= M) continue;
        #pragma unroll
        for (int j = 0; j < 4; j++) {
            int n = n0 + (tc << 2) + j;
            if (n < N)
                C[(size_t)m * N + n] = acc[i][j] + bias[n];
        }
    }
}

// ---------------- aggregation layer 1 (256 feats) + ReLU --------------------
// 64 threads per node (float4 each), 4 nodes per 256-thread block
__global__ void k_agg1() {
    int node = blockIdx.x * 4 + (threadIdx.x >> 6);
    int l = threadIdx.x & 63;
    if (node >= NN) return;
    const float4* h = (const float4*)g_h1;
    float d = g_dis[node];
    float sn = d * d;                       // self loop norm = 1/deg
    float4 v = h[(size_t)node * 64 + l];
    float ax = v.x * sn, ay = v.y * sn, az = v.z * sn, aw = v.w * sn;
    int beg = g_rowptr[node];
    int end = beg + g_count[node];
    for (int e = beg; e < end; e++) {
        int s = g_esrc[e];
        float w = g_enorm[e];
        float4 u = h[(size_t)s * 64 + l];
        ax += u.x * w; ay += u.y * w; az += u.z * w; aw += u.w * w;
    }
    float4 r = make_float4(fmaxf(ax, 0.f), fmaxf(ay, 0.f),
                           fmaxf(az, 0.f), fmaxf(aw, 0.f));
    ((float4*)g_a1)[(size_t)node * 64 + l] = r;
}

// ---------------- aggregation layer 2 (40 feats) + log_softmax --------------
// one warp per node; lane covers feature lane and lane+32 (lane<8)
__global__ void k_agg2(float* __restrict__ out) {
    int warp = (blockIdx.x * blockDim.x + threadIdx.x) >> 5;
    int lane = threadIdx.x & 31;
    if (warp >= NN) return;
    int node = warp;
    float d = g_dis[node];
    float sn = d * d;
    const float* h = g_h2;
    float a0 = h[(size_t)node * NC + lane] * sn;
    float a1 = (lane < 8) ? h[(size_t)node * NC + 32 + lane] * sn : 0.f;
    int beg = g_rowptr[node];
    int end = beg + g_count[node];
    for (int e = beg; e < end; e++) {
        int s = g_esrc[e];
        float w = g_enorm[e];
        a0 += h[(size_t)s * NC + lane] * w;
        if (lane < 8) a1 += h[(size_t)s * NC + 32 + lane] * w;
    }
    float mx = fmaxf(a0, (lane < 8) ? a1 : -CUDART_INF_F);
    #pragma unroll
    for (int off = 16; off; off >>= 1)
        mx = fmaxf(mx, __shfl_xor_sync(0xffffffffu, mx, off));
    float s0 = expf(a0 - mx) + ((lane < 8) ? expf(a1 - mx) : 0.f);
    #pragma unroll
    for (int off = 16; off; off >>= 1)
        s0 += __shfl_xor_sync(0xffffffffu, s0, off);
    float lse = mx + logf(s0);
    out[(size_t)node * NC + lane] = a0 - lse;
    if (lane < 8)
        out[(size_t)node * NC + 32 + lane] = a1 - lse;
}

// ---------------- launch ----------------------------------------------------
extern "C" void kernel_launch(void* const* d_in, const int* in_sizes, int n_in,
                              void* d_out, int out_size) {
    const float* x  = (const float*)d_in[0];
    const int*   ei = (const int*)d_in[1];
    const float* ew = (const float*)d_in[2];
    const float* W1 = (const float*)d_in[3];
    const float* b1 = (const float*)d_in[4];
    const float* W2 = (const float*)d_in[5];
    const float* b2 = (const float*)d_in[6];
    float* out = (float*)d_out;

    const int* esrc = ei;
    const int* edst = ei + NE;

    float *h1p, *a1p, *h2p;
    cudaGetSymbolAddress((void**)&h1p, g_h1);
    cudaGetSymbolAddress((void**)&a1p, g_a1);
    cudaGetSymbolAddress((void**)&h2p, g_h2);

    // graph preprocessing (CSR by dst, shared across both layers)
    k_init<<<(NN + 255) / 256, 256>>>();
    k_deg<<<(NE + 255) / 256, 256>>>(edst, ew);
    k_dis<<<(NN + 255) / 256, 256>>>();
    k_scan<<<1, 1024>>>();
    k_scatter<<<(NE + 255) / 256, 256>>>(esrc, edst, ew);

    // layer 1 (N=256, K=256 exact multiples for the 128x128 kernel)
    dim3 g1((NN + 127) / 128, FH / 128);
    k_gemm128<<<g1, 256>>>(x, W1, b1, h1p, NN, FH, FIN);
    k_agg1<<<(NN + 3) / 4, 256>>>();

    // layer 2 (N=40 -> guarded 64x64 kernel)
    dim3 g2((NN + 63) / 64, (NC + 63) / 64);
    k_gemm<<<g2, 256>>>(a1p, W2, b2, h2p, NN, NC, FH);
    k_agg2<<<(NN * 32 + 255) / 256, 256>>>(out);
}

// round 7
// speedup vs baseline: 1.1769x; 1.1769x over previous
#include <cuda_runtime.h>
#include <math_constants.h>
#include <math.h>

#define NN 100000
#define NE 1600000
#define FIN 256
#define FH 256
#define NC 40

#define SCAN_BS 1024
#define NSB ((NN + SCAN_BS - 1) / SCAN_BS)   // 98 scan blocks

// ---------------- scratch (static device globals; no allocation) ------------
__device__ float g_deg[NN];
__device__ float g_dis[NN];
__device__ int   g_count[NN];
__device__ int   g_rowptr[NN];
__device__ int   g_cursor[NN];
__device__ int   g_bsum[NSB];
__device__ int   g_boff[NSB];
__device__ int   g_esrc[NE];
__device__ float g_enorm[NE];
__device__ float g_h1[(size_t)NN * FH];   // x @ W1 + b1
__device__ float g_a1[(size_t)NN * FH];   // relu(aggregate(h1))
__device__ float g_h2[(size_t)NN * NC];   // a1 @ W2 + b2

// ---------------- graph preprocessing ---------------------------------------
__global__ void k_init() {
    int i = blockIdx.x * blockDim.x + threadIdx.x;
    if (i < NN) { g_deg[i] = 1.0f; g_count[i] = 0; }   // self-loop weight 1
}

__global__ void k_deg(const int* __restrict__ dst, const float* __restrict__ ew) {
    int e = blockIdx.x * blockDim.x + threadIdx.x;
    if (e < NE) {
        int d = dst[e];
        atomicAdd(&g_deg[d], ew[e]);
        atomicAdd(&g_count[d], 1);
    }
}

// phase 1: per-block exclusive scan of g_count -> g_rowptr (block-local) + totals
__global__ void k_scan1() {
    __shared__ int wsum[32];
    int tid = threadIdx.x;
    int lane = tid & 31, wid = tid >> 5;
    int i = blockIdx.x * SCAN_BS + tid;
    int v = (i < NN) ? g_count[i] : 0;
    int x = v;
    #pragma unroll
    for (int off = 1; off < 32; off <<= 1) {
        int t = __shfl_up_sync(0xffffffffu, x, off);
        if (lane >= off) x += t;
    }
    if (lane == 31) wsum[wid] = x;
    __syncthreads();
    if (wid == 0) {
        int s = wsum[lane];
        #pragma unroll
        for (int off = 1; off < 32; off <<= 1) {
            int t = __shfl_up_sync(0xffffffffu, s, off);
            if (lane >= off) s += t;
        }
        wsum[lane] = s;
    }
    __syncthreads();
    int ex = x - v + (wid > 0 ? wsum[wid - 1] : 0);
    if (i < NN) g_rowptr[i] = ex;
    if (tid == SCAN_BS - 1) g_bsum[blockIdx.x] = wsum[31];
}

// phase 2: single block scans the NSB block totals (exclusive)
__global__ void k_scan2() {
    __shared__ int sh[128];
    int tid = threadIdx.x;
    int v = (tid < NSB) ? g_bsum[tid] : 0;
    sh[tid] = v;
    __syncthreads();
    #pragma unroll
    for (int off = 1; off < 128; off <<= 1) {
        int t = (tid >= off) ? sh[tid - off] : 0;
        __syncthreads();
        sh[tid] += t;
        __syncthreads();
    }
    if (tid < NSB) g_boff[tid] = sh[tid] - v;   // exclusive
}

// phase 3: add block offsets, copy cursor, and compute dis = rsqrt(deg)
__global__ void k_scan3() {
    int i = blockIdx.x * SCAN_BS + threadIdx.x;
    if (i < NN) {
        int r = g_rowptr[i] + g_boff[blockIdx.x];
        g_rowptr[i] = r;
        g_cursor[i] = r;
        g_dis[i] = rsqrtf(g_deg[i]);            // deg >= 1 (self loop)
    }
}

__global__ void k_scatter(const int* __restrict__ src, const int* __restrict__ dst,
                          const float* __restrict__ ew) {
    int e = blockIdx.x * blockDim.x + threadIdx.x;
    if (e < NE) {
        int s = src[e], d = dst[e];
        int p = atomicAdd(&g_cursor[d], 1);
        g_esrc[p]  = s;
        g_enorm[p] = g_dis[s] * ew[e] * g_dis[d];
    }
}

// ---------------- big-tile fp32 GEMM for layer 1 ----------------------------
// C[M,256] = A[M,256] @ B[256,256] + bias. 128x128 tile, BK=8, 8x8/thread.
__global__ void k_gemm128(const float* __restrict__ A, const float* __restrict__ B,
                          const float* __restrict__ bias, float* __restrict__ C,
                          int M, int N, int K) {
    __shared__ float As[8][128];
    __shared__ float Bs[8][128];
    int tid = threadIdx.x;
    int m0 = blockIdx.x * 128;
    int n0 = blockIdx.y * 128;

    int ar = tid >> 1;              // A load row 0..127
    int ak = (tid & 1) << 2;        // A load k 0 or 4
    int bk = tid >> 5;              // B load k 0..7
    int bc = (tid & 31) << 2;       // B load col 0..124

    int tx = tid & 15;              // 0..15 -> n
    int ty = tid >> 4;              // 0..15 -> m

    float acc[8][8] = {};

    for (int k0 = 0; k0 < K; k0 += 8) {
        float4 av = make_float4(0.f, 0.f, 0.f, 0.f);
        int arow = m0 + ar;
        if (arow < M)
            av = *(const float4*)(A + (size_t)arow * K + k0 + ak);
        As[ak + 0][ar] = av.x;
        As[ak + 1][ar] = av.y;
        As[ak + 2][ar] = av.z;
        As[ak + 3][ar] = av.w;

        float4 bv = *(const float4*)(B + (size_t)(k0 + bk) * N + n0 + bc);
        *(float4*)&Bs[bk][bc] = bv;
        __syncthreads();

        #pragma unroll
        for (int kk = 0; kk < 8; kk++) {
            float a[8], b[8];
            *(float4*)&a[0] = *(float4*)&As[kk][ty << 3];
            *(float4*)&a[4] = *(float4*)&As[kk][(ty << 3) + 4];
            *(float4*)&b[0] = *(float4*)&Bs[kk][tx << 3];
            *(float4*)&b[4] = *(float4*)&Bs[kk][(tx << 3) + 4];
            #pragma unroll
            for (int i = 0; i < 8; i++)
                #pragma unroll
                for (int j = 0; j < 8; j++)
                    acc[i][j] += a[i] * b[j];
        }
        __syncthreads();
    }

    #pragma unroll
    for (int i = 0; i < 8; i++) {
        int m = m0 + (ty << 3) + i;
        if (m >= M) continue;
        float* crow = C + (size_t)m * N + n0 + (tx << 3);
        const float* brow = bias + n0 + (tx << 3);
        #pragma unroll
        for (int j = 0; j < 8; j++)
            crow[j] = acc[i][j] + brow[j];
    }
}

// ---------------- SIMT fp32 GEMM (guarded; used for layer 2, N=40) ----------
__global__ void k_gemm(const float* __restrict__ A, const float* __restrict__ B,
                       const float* __restrict__ bias, float* __restrict__ C,
                       int M, int N, int K) {
    __shared__ float As[16][64];   // transposed: As[k][m]
    __shared__ float Bs[16][64];   // Bs[k][n]
    int tid = threadIdx.x;
    int m0 = blockIdx.x * 64;
    int n0 = blockIdx.y * 64;
    int tr = tid >> 4;            // 0..15
    int tc = tid & 15;            // 0..15

    int lr = tid >> 2;            // A load: row 0..63
    int lk = (tid & 3) << 2;      // A load: k offset 0,4,8,12
    int bkr = tid >> 4;           // B load: k row 0..15
    int bc  = (tid & 15) << 2;    // B load: col 0..60

    float acc[4][4] = {};

    for (int k0 = 0; k0 < K; k0 += 16) {
        float4 av = make_float4(0.f, 0.f, 0.f, 0.f);
        int arow = m0 + lr;
        if (arow < M)
            av = *(const float4*)(A + (size_t)arow * K + k0 + lk);
        As[lk + 0][lr] = av.x;
        As[lk + 1][lr] = av.y;
        As[lk + 2][lr] = av.z;
        As[lk + 3][lr] = av.w;

        float4 bv = make_float4(0.f, 0.f, 0.f, 0.f);
        if (n0 + bc + 3 < N)
            bv = *(const float4*)(B + (size_t)(k0 + bkr) * N + n0 + bc);
        *(float4*)&Bs[bkr][bc] = bv;
        __syncthreads();

        #pragma unroll
        for (int kk = 0; kk < 16; kk++) {
            float4 a = *(float4*)&As[kk][tr << 2];
            float4 b = *(float4*)&Bs[kk][tc << 2];
            float ar[4] = {a.x, a.y, a.z, a.w};
            float br[4] = {b.x, b.y, b.z, b.w};
            #pragma unroll
            for (int i = 0; i < 4; i++)
                #pragma unroll
                for (int j = 0; j < 4; j++)
                    acc[i][j] += ar[i] * br[j];
        }
        __syncthreads();
    }

    #pragma unroll
    for (int i = 0; i < 4; i++) {
        int m = m0 + (tr << 2) + i;
        if (m >= M) continue;
        #pragma unroll
        for (int j = 0; j < 4; j++) {
            int n = n0 + (tc << 2) + j;
            if (n < N)
                C[(size_t)m * N + n] = acc[i][j] + bias[n];
        }
    }
}

// ---------------- aggregation layer 1 (256 feats) + ReLU --------------------
// 64 threads per node (float4 each), 4 nodes per 256-thread block
__global__ void k_agg1() {
    int node = blockIdx.x * 4 + (threadIdx.x >> 6);
    int l = threadIdx.x & 63;
    if (node >= NN) return;
    const float4* h = (const float4*)g_h1;
    float d = g_dis[node];
    float sn = d * d;                       // self loop norm = 1/deg
    float4 v = h[(size_t)node * 64 + l];
    float ax = v.x * sn, ay = v.y * sn, az = v.z * sn, aw = v.w * sn;
    int beg = g_rowptr[node];
    int end = beg + g_count[node];
    for (int e = beg; e < end; e++) {
        int s = g_esrc[e];
        float w = g_enorm[e];
        float4 u = h[(size_t)s * 64 + l];
        ax += u.x * w; ay += u.y * w; az += u.z * w; aw += u.w * w;
    }
    float4 r = make_float4(fmaxf(ax, 0.f), fmaxf(ay, 0.f),
                           fmaxf(az, 0.f), fmaxf(aw, 0.f));
    ((float4*)g_a1)[(size_t)node * 64 + l] = r;
}

// ---------------- aggregation layer 2 (40 feats) + log_softmax --------------
__global__ void k_agg2(float* __restrict__ out) {
    int warp = (blockIdx.x * blockDim.x + threadIdx.x) >> 5;
    int lane = threadIdx.x & 31;
    if (warp >= NN) return;
    int node = warp;
    float d = g_dis[node];
    float sn = d * d;
    const float* h = g_h2;
    float a0 = h[(size_t)node * NC + lane] * sn;
    float a1 = (lane < 8) ? h[(size_t)node * NC + 32 + lane] * sn : 0.f;
    int beg = g_rowptr[node];
    int end = beg + g_count[node];
    for (int e = beg; e < end; e++) {
        int s = g_esrc[e];
        float w = g_enorm[e];
        a0 += h[(size_t)s * NC + lane] * w;
        if (lane < 8) a1 += h[(size_t)s * NC + 32 + lane] * w;
    }
    float mx = fmaxf(a0, (lane < 8) ? a1 : -CUDART_INF_F);
    #pragma unroll
    for (int off = 16; off; off >>= 1)
        mx = fmaxf(mx, __shfl_xor_sync(0xffffffffu, mx, off));
    float s0 = expf(a0 - mx) + ((lane < 8) ? expf(a1 - mx) : 0.f);
    #pragma unroll
    for (int off = 16; off; off >>= 1)
        s0 += __shfl_xor_sync(0xffffffffu, s0, off);
    float lse = mx + logf(s0);
    out[(size_t)node * NC + lane] = a0 - lse;
    if (lane < 8)
        out[(size_t)node * NC + 32 + lane] = a1 - lse;
}

// ---------------- launch ----------------------------------------------------
extern "C" void kernel_launch(void* const* d_in, const int* in_sizes, int n_in,
                              void* d_out, int out_size) {
    const float* x  = (const float*)d_in[0];
    const int*   ei = (const int*)d_in[1];
    const float* ew = (const float*)d_in[2];
    const float* W1 = (const float*)d_in[3];
    const float* b1 = (const float*)d_in[4];
    const float* W2 = (const float*)d_in[5];
    const float* b2 = (const float*)d_in[6];
    float* out = (float*)d_out;

    const int* esrc = ei;
    const int* edst = ei + NE;

    float *h1p, *a1p, *h2p;
    cudaGetSymbolAddress((void**)&h1p, g_h1);
    cudaGetSymbolAddress((void**)&a1p, g_a1);
    cudaGetSymbolAddress((void**)&h2p, g_h2);

    // graph preprocessing (CSR by dst, shared across both layers)
    k_init<<<(NN + 255) / 256, 256>>>();
    k_deg<<<(NE + 255) / 256, 256>>>(edst, ew);
    k_scan1<<<NSB, SCAN_BS>>>();
    k_scan2<<<1, 128>>>();
    k_scan3<<<NSB, SCAN_BS>>>();          // also computes g_dis
    k_scatter<<<(NE + 255) / 256, 256>>>(esrc, edst, ew);

    // layer 1 (N=256, K=256 exact multiples for the 128x128 kernel)
    dim3 g1((NN + 127) / 128, FH / 128);
    k_gemm128<<<g1, 256>>>(x, W1, b1, h1p, NN, FH, FIN);
    k_agg1<<<(NN + 3) / 4, 256>>>();

    // layer 2 (N=40 -> guarded 64x64 kernel)
    dim3 g2((NN + 63) / 64, (NC + 63) / 64);
    k_gemm<<<g2, 256>>>(a1p, W2, b2, h2p, NN, NC, FH);
    k_agg2<<<(NN * 32 + 255) / 256, 256>>>(out);
}